// round 14
// baseline (speedup 1.0000x reference)
#include <cuda_runtime.h>
#include <math.h>

// Problem constants
#define B    32
#define T    256
#define D    256
#define HID  1024
#define G3   3072
#define OO   256
#define ALPHA 0.001f
#define ONEMA 0.999f

#define NBLK 128          // one block per 8 output columns (128*8 = 1024)
#define THR  512          // 16 warps = 16 k-chunks (per layer)
#define KT0  (HID + D)    // 1280 (layer-0 total K)

typedef unsigned long long u64;

// ---------------- static device scratch (allocation-free) ----------------
__device__ float g_W0p[(size_t)NBLK * KT0 * 24];   // L0 weights blocked [jt][k][24]
__device__ float g_WT1[(2 * HID) * G3];            // L1 weights k-major [k][3072]
__device__ float g_xT[(size_t)T * D * 32];         // transposed input [t*D+d][b]
__device__ float g_o0r[2][HID * 32];               // L0 event ring [slot][j][b]
__device__ float g_sh0[2][HID * 32];               // h0 = o*c, double-buffered
__device__ float g_sh1[2][HID * 32];               // h1 = o*c, double-buffered
__device__ unsigned g_bar_cnt;
__device__ volatile unsigned g_bar_gen;

__device__ __forceinline__ float sigmoidf_(float v) { return 1.0f / (1.0f + expf(-v)); }

__device__ __forceinline__ void ffma2(u64& d, u64 a, u64 b) {
    asm("fma.rn.f32x2 %0, %1, %2, %0;" : "+l"(d) : "l"(a), "l"(b));
}
__device__ __forceinline__ u64 packdup(float a) {
    u64 r; unsigned ua = __float_as_uint(a);
    asm("mov.b64 %0, {%1, %1};" : "=l"(r) : "r"(ua));
    return r;
}
__device__ __forceinline__ void unpack2(u64 v, float& lo, float& hi) {
    unsigned l, h;
    asm("mov.b64 {%0, %1}, %2;" : "=r"(l), "=r"(h) : "l"(v));
    lo = __uint_as_float(l); hi = __uint_as_float(h);
}

// ---------------- grid-wide barrier (round-10 version) ----------------
__device__ __forceinline__ void gbar(unsigned target) {
    __syncthreads();
    if (threadIdx.x == 0) {
        __threadfence();
        unsigned old = atomicAdd(&g_bar_cnt, 1u);
        if (old == NBLK - 1u) {
            g_bar_cnt = 0u;
            __threadfence();
            g_bar_gen = target;
        } else {
            while (g_bar_gen != target) { }
        }
        __threadfence();
    }
    __syncthreads();
}

// ---------------- L0 pack: blocked [jt][k][24] = [u8|r8|c8] per k ----------
__global__ void pack0_kernel(const float* __restrict__ w_hh0,
                             const float* __restrict__ w_ih0) {
    size_t idx = (size_t)blockIdx.x * 256 + threadIdx.x;   // = col * KT0 + k
    if (idx >= (size_t)G3 * KT0) return;
    int col = (int)(idx / KT0);
    int k = (int)(idx - (size_t)col * KT0);
    int g = col >> 10;            // gate
    int j = col & 1023;
    int jt = j >> 3, jj = j & 7;
    float v = (k < HID) ? w_hh0[(size_t)col * HID + k]
                        : w_ih0[(size_t)col * D + (k - HID)];
    g_W0p[((size_t)jt * KT0 + k) * 24 + g * 8 + jj] = v;
}

// ---------------- L1 pack: g_WT1[k + rowOff][col] = src[col][k] ------------
__global__ void pack1_kernel(const float* __restrict__ src, int K, int rowOff) {
    __shared__ float tile[32][33];
    int kBase = blockIdx.x * 32;
    int colBase = blockIdx.y * 32;
    int tx = threadIdx.x, ty = threadIdx.y;   // (32, 8)
#pragma unroll
    for (int i = 0; i < 32; i += 8) {
        int col = colBase + ty + i;
        tile[ty + i][tx] = src[(size_t)col * K + kBase + tx];
    }
    __syncthreads();
#pragma unroll
    for (int i = 0; i < 32; i += 8) {
        int k = kBase + ty + i;
        g_WT1[(size_t)(k + rowOff) * G3 + colBase + tx] = tile[tx][ty + i];
    }
}

// ---------------- x transpose + state/barrier init (fused) ----------------
__global__ void xpose_kernel(const float* __restrict__ x) {
    __shared__ float tile[32][33];
    int col0 = blockIdx.x * 32;               // td tile
    int tx = threadIdx.x, ty = threadIdx.y;   // (32, 8)
    int tid = ty * 32 + tx;
    int gidx = blockIdx.x * 256 + tid;
    if (gidx < HID * 32) {
        g_sh0[0][gidx] = 0.0f; g_sh0[1][gidx] = 0.0f;
        g_sh1[0][gidx] = 0.0f; g_sh1[1][gidx] = 0.0f;
        g_o0r[0][gidx] = 0.0f; g_o0r[1][gidx] = 0.0f;
    }
    if (gidx == 0) { g_bar_cnt = 0u; g_bar_gen = 0u; }
#pragma unroll
    for (int i = 0; i < 32; i += 8) {
        int b = ty + i;
        tile[b][tx] = x[(size_t)b * (T * D) + col0 + tx];
    }
    __syncthreads();
#pragma unroll
    for (int i = 0; i < 32; i += 8) {
        int td = col0 + ty + i;
        g_xT[(size_t)td * 32 + tx] = tile[tx][ty + i];
    }
}

// store 2 gates (8 floats each) into an exchange row (pitch 17)
__device__ __forceinline__ void store16(float* p, const u64* a, const u64* b) {
    float lo, hi;
    unpack2(a[0], lo, hi); p[0] = lo; p[1] = hi;
    unpack2(a[1], lo, hi); p[2] = lo; p[3] = hi;
    unpack2(a[2], lo, hi); p[4] = lo; p[5] = hi;
    unpack2(a[3], lo, hi); p[6] = lo; p[7] = hi;
    unpack2(b[0], lo, hi); p[8]  = lo; p[9]  = hi;
    unpack2(b[1], lo, hi); p[10] = lo; p[11] = hi;
    unpack2(b[2], lo, hi); p[12] = lo; p[13] = hi;
    unpack2(b[3], lo, hi); p[14] = lo; p[15] = hi;
}

// One k-segment of GEMM with 8-deep activation prefetch (round-10 form).
// Works for smem OR global weight pointers (wr). cnt multiple of 8.
// Accumulation order = serial k-ascending (bitwise stable).
#define GEMM_SEG(cnt, aptr, AC)                                              \
    for (int kt = 0; kt < (cnt); kt += 8) {                                  \
        float a8[8];                                                         \
        _Pragma("unroll")                                                    \
        for (int i = 0; i < 8; i++) a8[i] = (aptr)[(size_t)(kt + i) * 32];   \
        _Pragma("unroll")                                                    \
        for (int i = 0; i < 8; i++) {                                        \
            u64 aa = packdup(a8[i]);                                         \
            longlong2 p0 = wr[0], p1 = wr[1], p2 = wr[2];                    \
            longlong2 p3 = wr[3], p4 = wr[4], p5 = wr[5];                    \
            ffma2(aU[0], (u64)p0.x, aa); ffma2(aU[1], (u64)p0.y, aa);        \
            ffma2(aU[2], (u64)p1.x, aa); ffma2(aU[3], (u64)p1.y, aa);        \
            ffma2(aR[0], (u64)p2.x, aa); ffma2(aR[1], (u64)p2.y, aa);        \
            ffma2(aR[2], (u64)p3.x, aa); ffma2(aR[3], (u64)p3.y, aa);        \
            ffma2(AC[0], (u64)p4.x, aa); ffma2(AC[1], (u64)p4.y, aa);        \
            ffma2(AC[2], (u64)p5.x, aa); ffma2(AC[3], (u64)p5.y, aa);        \
            wr += 6;                                                         \
        }                                                                    \
    }

// ---------------- fused two-layer persistent scan ----------------
// Step s: L0 processes t=s (s<256), then L1 processes t=s-1 (s>=1).
// ONE grid barrier per fused step (257 total vs 512).
// Warp w = chunk w of each layer; per-gate chunk sums serial s=0..15
// (bitwise identical to round 10). Register-resident states:
// tid<256 hold L1 element (b,j); tid>=256 hold L0 element (b,j).
__global__ __launch_bounds__(THR, 1) void scan_fused(
    const float* __restrict__ bias0, const float* __restrict__ thr0,
    const float* __restrict__ bias1, const float* __restrict__ thr1,
    float* __restrict__ hs, float* __restrict__ cs,
    float* __restrict__ os, float* __restrict__ is_)
{
    extern __shared__ float smem[];
    float* s_w = smem;                               // [2048][24] L1 weights
    float* s_p = smem + 2 * HID * 24;                // [16][32] pitch-17 exchange

    const int tid  = threadIdx.x;
    const int lane = tid & 31;                       // = batch in GEMM
    const int wrp  = tid >> 5;                       // = chunk index
    const int jb   = blockIdx.x * 8;

    // ---- stage L1 weights into smem once ----
    for (int i = tid; i < 2 * HID * 6; i += THR) {
        int k = i / 6, c = i - k * 6;
        int g = c >> 1, half = c & 1;
        float4 v = *(const float4*)(g_WT1 + (size_t)k * G3 + g * HID + jb + half * 4);
        ((float4*)(s_w + k * 24))[c] = v;
    }

    // ---- per-thread update constants + register state ----
    const int fj = tid & 7;
    const int fb = (tid & 255) >> 3;
    const int jg = jb + fj;
    float thv, bU, bR, bC;
    if (tid < 256) {                                 // L1 element
        thv = sigmoidf_(thr1[jg]);
        bU = bias1[jg]; bR = bias1[HID + jg]; bC = bias1[2 * HID + jg];
    } else {                                         // L0 element
        thv = sigmoidf_(thr0[jg]);
        bU = bias0[jg]; bR = bias0[HID + jg]; bC = bias0[2 * HID + jg];
    }
    float rc = 0.f, ro = 0.f, riu = 0.f, rir = 0.f, ric = 0.f;
    __syncthreads();

    // ---- chunk geometry ----
    const int k00 = wrp * 80;                        // L0: CK=80
    int hE0 = HID - k00;
    if (hE0 < 0) hE0 = 0;
    if (hE0 > 80) hE0 = 80;
    const int xC0 = 80 - hE0;
    const int kx00 = k00 + hE0 - HID;                // valid iff xC0>0
    const longlong2* const w0base =
        (const longlong2*)(g_W0p + ((size_t)blockIdx.x * KT0 + k00) * 24);

    const int k01 = wrp * 128;                       // L1: CK=128
    const bool l1hid = (wrp < 8);
    const int kx01 = k01 - HID;                      // valid iff !l1hid
    const longlong2* const w1base = (const longlong2*)(s_w + (size_t)k01 * 24);

    float* myrow = s_p + (wrp * 32 + lane) * 17;
    unsigned gen = 0;

    for (int s = 0; s <= T; s++) {
        const int rd = s & 1;
        u64 aU[4], aR[4], aCH[4], aCX[4];

        // ================= L0: GEMM (t = s) =================
        if (s < T) {
#pragma unroll
            for (int i = 0; i < 4; i++) { aU[i] = 0; aR[i] = 0; aCH[i] = 0; aCX[i] = 0; }
            const longlong2* wr = w0base;
            if (hE0 > 0) {
                const float* ah = g_sh0[rd] + (size_t)k00 * 32 + lane;
                GEMM_SEG(hE0, ah, aCH)
            }
            if (xC0 > 0) {
                const float* ax = g_xT + ((size_t)s * D + kx00) * 32 + lane;
                GEMM_SEG(xC0, ax, aCX)
            }
            store16(myrow, aU, aR);
        }
        __syncthreads();
        float su0 = 0.f, sr0 = 0.f;
        if (s < T && tid >= 256) {
#pragma unroll
            for (int ss = 0; ss < 16; ss++) {
                const float* q = s_p + (ss * 32 + fb) * 17;
                su0 += q[fj];
                sr0 += q[8 + fj];
            }
        }
        __syncthreads();
        if (s < T) store16(myrow, aCH, aCX);
        __syncthreads();
        if (s < T && tid >= 256) {                   // L0 update (t = s)
            float sch = 0.f, scx = 0.f;
#pragma unroll
            for (int ss = 0; ss < 16; ss++) {
                const float* q = s_p + (ss * 32 + fb) * 17;
                if (ss < 13) sch += q[fj];
                if (ss >= 12) scx += q[8 + fj];
            }
            float niu = ALPHA * riu + ONEMA * (su0 + bU);
            float u = sigmoidf_(niu);
            float nir = ALPHA * rir + ONEMA * (sr0 + bR);
            float r = sigmoidf_(nir);
            float nic = ALPHA * ric + ONEMA * (scx + r * sch + bC);
            float z = tanhf(nic);
            float creset = rc - ro * thv;
            float nc = (1.0f - u) * creset + u * z;
            float no = (nc - thv > 0.0f) ? 1.0f : 0.0f;
            rc = nc; ro = no; riu = niu; rir = nir; ric = nic;
            g_o0r[rd][jg * 32 + fb] = no;            // ring slot s&1
            g_sh0[rd ^ 1][jg * 32 + fb] = no * nc;
        }

        // ================= L1: GEMM (t = s-1) =================
        if (s >= 1) {
#pragma unroll
            for (int i = 0; i < 4; i++) { aU[i] = 0; aR[i] = 0; aCH[i] = 0; aCX[i] = 0; }
            const longlong2* wr = w1base;
            if (l1hid) {
                const float* ah = g_sh1[rd] + (size_t)k01 * 32 + lane;
                GEMM_SEG(128, ah, aCH)
            } else {
                const float* ax = g_o0r[rd ^ 1] + (size_t)kx01 * 32 + lane;   // o0[s-1]
                GEMM_SEG(128, ax, aCX)
            }
        }
        __syncthreads();                             // guard s_p reuse
        if (s >= 1) store16(myrow, aU, aR);
        __syncthreads();
        float su1 = 0.f, sr1 = 0.f;
        if (s >= 1 && tid < 256) {
#pragma unroll
            for (int ss = 0; ss < 16; ss++) {
                const float* q = s_p + (ss * 32 + fb) * 17;
                su1 += q[fj];
                sr1 += q[8 + fj];
            }
        }
        __syncthreads();
        if (s >= 1) store16(myrow, aCH, aCX);
        __syncthreads();
        if (s >= 1 && tid < 256) {                   // L1 update (t = s-1)
            float sch = 0.f, scx = 0.f;
#pragma unroll
            for (int ss = 0; ss < 16; ss++) {
                const float* q = s_p + (ss * 32 + fb) * 17;
                if (ss < 8) sch += q[fj];
                if (ss >= 8) scx += q[8 + fj];
            }
            float niu = ALPHA * riu + ONEMA * (su1 + bU);
            float u = sigmoidf_(niu);
            float nir = ALPHA * rir + ONEMA * (sr1 + bR);
            float r = sigmoidf_(nir);
            float nic = ALPHA * ric + ONEMA * (scx + r * sch + bC);
            float z = tanhf(nic);
            float creset = rc - ro * thv;
            float nc = (1.0f - u) * creset + u * z;
            float no = (nc - thv > 0.0f) ? 1.0f : 0.0f;
            rc = nc; ro = no; riu = niu; rir = nir; ric = nic;
            g_sh1[rd ^ 1][jg * 32 + fb] = no * nc;

            int t = s - 1;
            size_t ho = (size_t)t * (B * HID) + fb * HID + jg;
            hs[ho] = no * nc;
            cs[ho] = nc;
            os[ho] = no;
            size_t io = (size_t)t * (B * G3) + (size_t)fb * G3 + jg;
            is_[io] = niu;
            is_[io + HID] = nir;
            is_[io + 2 * HID] = nic;
        }
        gbar(++gen);
    }
}

// ---------------- softmax head ----------------
__global__ void head_kernel(const float* __restrict__ hLast,
                            const float* __restrict__ w_out,
                            const float* __restrict__ b_out,
                            float* __restrict__ pred)
{
    __shared__ float sh_h[HID];
    __shared__ float red[OO];
    int b = blockIdx.x, tid = threadIdx.x;
    for (int i = tid; i < HID; i += OO) sh_h[i] = hLast[b * HID + i];
    __syncthreads();

    float acc = 0.0f;
    const float* w = w_out + (size_t)tid * HID;
#pragma unroll 4
    for (int k = 0; k < HID; k++) acc += w[k] * sh_h[k];
    float logit = acc + b_out[tid];

    red[tid] = logit; __syncthreads();
    for (int s = 128; s > 0; s >>= 1) { if (tid < s) red[tid] = fmaxf(red[tid], red[tid + s]); __syncthreads(); }
    float mx = red[0]; __syncthreads();
    float e = expf(logit - mx);
    red[tid] = e; __syncthreads();
    for (int s = 128; s > 0; s >>= 1) { if (tid < s) red[tid] += red[tid + s]; __syncthreads(); }
    float sum = red[0];
    pred[b * OO + tid] = e / sum;
}

// ---------------- launch ----------------
extern "C" void kernel_launch(void* const* d_in, const int* in_sizes, int n_in,
                              void* d_out, int out_size) {
    const float* x     = (const float*)d_in[0];
    const float* w_ih0 = (const float*)d_in[1];
    const float* w_hh0 = (const float*)d_in[2];
    const float* bias0 = (const float*)d_in[3];
    const float* thr0  = (const float*)d_in[4];
    const float* w_ih1 = (const float*)d_in[6];
    const float* w_hh1 = (const float*)d_in[7];
    const float* bias1 = (const float*)d_in[8];
    const float* thr1  = (const float*)d_in[9];
    const float* w_out = (const float*)d_in[11];
    const float* b_out = (const float*)d_in[12];

    float* out  = (float*)d_out;
    float* pred = out;
    float* hs   = out + B * OO;
    float* cs   = hs + (size_t)T * B * HID;
    float* os   = cs + (size_t)T * B * HID;
    float* is_  = os + (size_t)T * B * HID;

    const int SMEM = 2 * HID * 24 * 4 + 16 * 32 * 17 * 4;     // 231,424 B
    cudaFuncSetAttribute(scan_fused, cudaFuncAttributeMaxDynamicSharedMemorySize, SMEM);

    dim3 tpt(32, 8);
    pack0_kernel<<<(int)(((size_t)G3 * KT0 + 255) / 256), 256>>>(w_hh0, w_ih0);
    pack1_kernel<<<dim3(HID / 32, G3 / 32), tpt>>>(w_hh1, HID, 0);
    pack1_kernel<<<dim3(HID / 32, G3 / 32), tpt>>>(w_ih1, HID, HID);
    xpose_kernel<<<T * D / 32, tpt>>>(x);          // also zeroes states + barrier

    scan_fused<<<NBLK, THR, SMEM>>>(bias0, thr0, bias1, thr1, hs, cs, os, is_);

    head_kernel<<<B, OO>>>(hs + (size_t)(T - 1) * B * HID, w_out, b_out, pred);
}

// round 15
// speedup vs baseline: 1.2433x; 1.2433x over previous
#include <cuda_runtime.h>
#include <math.h>

// Problem constants
#define B    32
#define T    256
#define D    256
#define HID  1024
#define G3   3072
#define OO   256
#define ALPHA 0.001f
#define ONEMA 0.999f

#define NBLK 128          // one block per 8 output columns (128*8 = 1024)
#define THR  512          // 16 warps = 16 k-chunks

typedef unsigned long long u64;

// ---------------- static device scratch (allocation-free) ----------------
__device__ float g_WT0[(HID + D) * G3];        // 1280 x 3072 k-major
__device__ float g_WT1[(2 * HID) * G3];        // 2048 x 3072 k-major
__device__ float g_xT[(size_t)T * D * 32];     // transposed input [t*D+d][b]
__device__ float g_o0[(size_t)T * HID * 32];   // layer0 events [t][j][b]
__device__ float g_sh0[2][HID * 32];           // L0 h = o*c, double-buffered
__device__ float g_sh1[2][HID * 32];           // L1 h = o*c, double-buffered
__device__ unsigned g_bar_cnt0, g_bar_cnt1;
__device__ volatile unsigned g_bar_gen0;
__device__ volatile unsigned g_bar_gen1;

__device__ __forceinline__ float sigmoidf_(float v) { return 1.0f / (1.0f + expf(-v)); }

__device__ __forceinline__ void ffma2(u64& d, u64 a, u64 b) {
    asm("fma.rn.f32x2 %0, %1, %2, %0;" : "+l"(d) : "l"(a), "l"(b));
}
__device__ __forceinline__ u64 packdup(float a) {
    u64 r; unsigned ua = __float_as_uint(a);
    asm("mov.b64 %0, {%1, %1};" : "=l"(r) : "r"(ua));
    return r;
}
__device__ __forceinline__ void unpack2(u64 v, float& lo, float& hi) {
    unsigned l, h;
    asm("mov.b64 {%0, %1}, %2;" : "=r"(l), "=r"(h) : "l"(v));
    lo = __uint_as_float(l); hi = __uint_as_float(h);
}

// ---------------- grid-wide barrier (round-10 version, per-layer vars) --------
template <int LAYER>
__device__ __forceinline__ void gbar(unsigned target) {
    unsigned* cnt = (LAYER == 0) ? &g_bar_cnt0 : &g_bar_cnt1;
    volatile unsigned* gen = (LAYER == 0) ? &g_bar_gen0 : &g_bar_gen1;
    __syncthreads();
    if (threadIdx.x == 0) {
        __threadfence();
        unsigned old = atomicAdd(cnt, 1u);
        if (old == NBLK - 1u) {
            *cnt = 0u;
            __threadfence();
            *gen = target;
        } else {
            while (*gen != target) { }
        }
        __threadfence();
    }
    __syncthreads();
}

// ---------------- weight pack: dst[k][col] = src[col][k] ----------------
__global__ void pack_kernel(const float* __restrict__ src, int dstSel, int K, int rowOff) {
    __shared__ float tile[32][33];
    float* dst = dstSel ? g_WT1 : g_WT0;
    int kBase = blockIdx.x * 32;
    int colBase = blockIdx.y * 32;
    int tx = threadIdx.x, ty = threadIdx.y;   // (32, 8)
#pragma unroll
    for (int i = 0; i < 32; i += 8) {
        int col = colBase + ty + i;
        tile[ty + i][tx] = src[(size_t)col * K + kBase + tx];
    }
    __syncthreads();
#pragma unroll
    for (int i = 0; i < 32; i += 8) {
        int k = kBase + ty + i;
        dst[(size_t)(k + rowOff) * G3 + colBase + tx] = tile[tx][ty + i];
    }
}

// ---------------- x transpose + ALL state/barrier init (fused) ----------------
__global__ void xpose_kernel(const float* __restrict__ x) {
    __shared__ float tile[32][33];
    int col0 = blockIdx.x * 32;               // td tile
    int tx = threadIdx.x, ty = threadIdx.y;   // (32, 8)
    int tid = ty * 32 + tx;
    int gidx = blockIdx.x * 256 + tid;
    if (gidx < HID * 32) {
        g_sh0[0][gidx] = 0.0f; g_sh0[1][gidx] = 0.0f;
        g_sh1[0][gidx] = 0.0f; g_sh1[1][gidx] = 0.0f;
    }
    if (gidx == 0) {
        g_bar_cnt0 = 0u; g_bar_gen0 = 0u;
        g_bar_cnt1 = 0u; g_bar_gen1 = 0u;
    }
#pragma unroll
    for (int i = 0; i < 32; i += 8) {
        int b = ty + i;
        tile[b][tx] = x[(size_t)b * (T * D) + col0 + tx];
    }
    __syncthreads();
#pragma unroll
    for (int i = 0; i < 32; i += 8) {
        int td = col0 + ty + i;
        g_xT[(size_t)td * 32 + tx] = tile[tx][ty + i];
    }
}

// store 2 gates (8 floats each) into exchange buffer row, pitch 17
__device__ __forceinline__ void store16(float* p, const u64* a, const u64* b) {
    float lo, hi;
    unpack2(a[0], lo, hi); p[0] = lo; p[1] = hi;
    unpack2(a[1], lo, hi); p[2] = lo; p[3] = hi;
    unpack2(a[2], lo, hi); p[4] = lo; p[5] = hi;
    unpack2(a[3], lo, hi); p[6] = lo; p[7] = hi;
    unpack2(b[0], lo, hi); p[8]  = lo; p[9]  = hi;
    unpack2(b[1], lo, hi); p[10] = lo; p[11] = hi;
    unpack2(b[2], lo, hi); p[12] = lo; p[13] = hi;
    unpack2(b[3], lo, hi); p[14] = lo; p[15] = hi;
}

// One k-segment of GEMM with 8-deep activation prefetch (round-10 form).
// cnt is a multiple of 8. Accumulation order = serial k-ascending (bitwise).
#define GEMM_SEG(cnt, aptr, AC)                                              \
    for (int kt = 0; kt < (cnt); kt += 8) {                                  \
        float a8[8];                                                         \
        _Pragma("unroll")                                                    \
        for (int i = 0; i < 8; i++) a8[i] = (aptr)[(size_t)(kt + i) * 32];   \
        _Pragma("unroll")                                                    \
        for (int i = 0; i < 8; i++) {                                        \
            u64 aa = packdup(a8[i]);                                         \
            longlong2 p0 = wr[0], p1 = wr[1], p2 = wr[2];                    \
            longlong2 p3 = wr[3], p4 = wr[4], p5 = wr[5];                    \
            ffma2(aU[0], (u64)p0.x, aa); ffma2(aU[1], (u64)p0.y, aa);        \
            ffma2(aU[2], (u64)p1.x, aa); ffma2(aU[3], (u64)p1.y, aa);        \
            ffma2(aR[0], (u64)p2.x, aa); ffma2(aR[1], (u64)p2.y, aa);        \
            ffma2(aR[2], (u64)p3.x, aa); ffma2(aR[3], (u64)p3.y, aa);        \
            ffma2(AC[0], (u64)p4.x, aa); ffma2(AC[1], (u64)p4.y, aa);        \
            ffma2(AC[2], (u64)p5.x, aa); ffma2(AC[3], (u64)p5.y, aa);        \
            wr += 6;                                                         \
        }                                                                    \
    }

// ---------------- persistent scan kernel (round-10 structure) ----------------
// grid = 128 blocks, each owns 8 j-columns; warp w = contiguous k-chunk w.
// All 16 warps GEMM concurrently; per-gate chunk sums in serial s=0..15 order.
// Register-resident c/o/i state. Final-step grid barrier skipped.
template <int LAYER>
__global__ __launch_bounds__(THR, 1) void scan_kernel(
    const float* __restrict__ bias,
    const float* __restrict__ thr_raw,
    float* __restrict__ hs, float* __restrict__ cs,
    float* __restrict__ os, float* __restrict__ is_)
{
    constexpr int KX    = (LAYER == 0) ? D : HID;    // x-part K
    constexpr int KT    = HID + KX;                  // total K
    constexpr int CK    = KT / 16;                   // 80 / 128 per warp-chunk
    constexpr int CH_HI = (LAYER == 0) ? 13 : 8;     // chunks with hidden rows
    constexpr int CX_LO = (LAYER == 0) ? 12 : 8;     // chunks with x rows
    const float* __restrict__ WT = (LAYER == 0) ? g_WT0 : g_WT1;

    extern __shared__ float smem[];
    float* s_w = smem;                               // [KT][24]
    float* s_p = smem + KT * 24;                     // [16][32] pitch 17 exchange

    const int tid  = threadIdx.x;
    const int lane = tid & 31;                       // = batch in GEMM
    const int wrp  = tid >> 5;                       // = k-chunk index
    const int jb   = blockIdx.x * 8;                 // block's 8 j-columns

    // ---- stage weights into smem once ----
    for (int i = tid; i < KT * 6; i += THR) {
        int k = i / 6, c = i - k * 6;
        int g = c >> 1, half = c & 1;
        float4 v = *(const float4*)(WT + (size_t)k * G3 + g * HID + jb + half * 4);
        ((float4*)(s_w + k * 24))[c] = v;
    }

    // update-phase constants + register state (tid<256: fj=tid&7, fb=tid>>3)
    const int fj = tid & 7;
    const int fb = tid >> 3;
    const int jg = jb + fj;
    float thv = 0.f, bU = 0.f, bR = 0.f, bC = 0.f;
    float rc = 0.f, ro = 0.f, riu = 0.f, rir = 0.f, ric = 0.f;   // c,o,i state
    if (tid < 256) {
        thv = sigmoidf_(thr_raw[jg]);
        bU = bias[jg]; bR = bias[HID + jg]; bC = bias[2 * HID + jg];
    }
    __syncthreads();

    const int k0 = wrp * CK;
    int hEnd = HID - k0;                             // hidden rows in this chunk
    if (hEnd < 0) hEnd = 0;
    if (hEnd > CK) hEnd = CK;
    const int xCnt = CK - hEnd;
    const int kx0 = k0 + hEnd - HID;                 // x-row start (valid iff xCnt>0)
    float* myrow = s_p + (wrp * 32 + lane) * 17;

    unsigned gen = 0;

    for (int t = 0; t < T; t++) {
        const float* __restrict__ shR = (LAYER == 0) ? g_sh0[t & 1] : g_sh1[t & 1];
        float* __restrict__ shW = (LAYER == 0) ? g_sh0[(t & 1) ^ 1] : g_sh1[(t & 1) ^ 1];

        // ---- GEMM: serial over this warp's contiguous chunk, 8-deep prefetch ----
        u64 aU[4], aR[4], aCH[4], aCX[4];
#pragma unroll
        for (int i = 0; i < 4; i++) { aU[i] = 0; aR[i] = 0; aCH[i] = 0; aCX[i] = 0; }

        const longlong2* wr = (const longlong2*)(s_w + (size_t)k0 * 24);
        if (hEnd > 0) {                              // hidden rows -> aCH
            const float* ah = shR + (size_t)k0 * 32 + lane;
            GEMM_SEG(hEnd, ah, aCH)
        }
        if (xCnt > 0) {                              // x rows -> aCX
            const float* ax = (LAYER == 0)
                ? g_xT + ((size_t)t * D + kx0) * 32 + lane
                : g_o0 + ((size_t)t * HID + kx0) * 32 + lane;
            GEMM_SEG(xCnt, ax, aCX)
        }

        // ---- exchange round 1: U, R ----
        store16(myrow, aU, aR);
        __syncthreads();
        float su = 0.f, sr = 0.f;
        if (tid < 256) {
#pragma unroll
            for (int s = 0; s < 16; s++) {
                const float* q = s_p + (s * 32 + fb) * 17;
                su += q[fj];
                sr += q[8 + fj];
            }
        }
        __syncthreads();

        // ---- exchange round 2: CH, CX ----
        store16(myrow, aCH, aCX);
        __syncthreads();
        float sch = 0.f, scx = 0.f;
        if (tid < 256) {
#pragma unroll
            for (int s = 0; s < 16; s++) {
                const float* q = s_p + (s * 32 + fb) * 17;
                if (s < CH_HI) sch += q[fj];
                if (s >= CX_LO) scx += q[8 + fj];
            }
        }

        // ---- EGRU update: one (b, j) per thread, register state ----
        if (tid < 256) {
            float niu = ALPHA * riu + ONEMA * (su + bU);
            float u = sigmoidf_(niu);
            float nir = ALPHA * rir + ONEMA * (sr + bR);
            float r = sigmoidf_(nir);
            float nic = ALPHA * ric + ONEMA * (scx + r * sch + bC);
            float z = tanhf(nic);

            float creset = rc - ro * thv;
            float nc = (1.0f - u) * creset + u * z;
            float no = (nc - thv > 0.0f) ? 1.0f : 0.0f;

            rc = nc; ro = no; riu = niu; rir = nir; ric = nic;

            shW[jg * 32 + fb] = no * nc;

            if (LAYER == 0) {
                g_o0[((size_t)t * HID + jg) * 32 + fb] = no;
            } else {
                size_t ho = (size_t)t * (B * HID) + fb * HID + jg;
                hs[ho] = no * nc;
                cs[ho] = nc;
                os[ho] = no;
                size_t io = (size_t)t * (B * G3) + (size_t)fb * G3 + jg;
                is_[io] = niu;
                is_[io + HID] = nir;
                is_[io + 2 * HID] = nic;
            }
        }
        if (t + 1 < T) gbar<LAYER>(++gen);           // final-step barrier skipped
    }
}

// ---------------- softmax head ----------------
__global__ void head_kernel(const float* __restrict__ hLast,
                            const float* __restrict__ w_out,
                            const float* __restrict__ b_out,
                            float* __restrict__ pred)
{
    __shared__ float sh_h[HID];
    __shared__ float red[OO];
    int b = blockIdx.x, tid = threadIdx.x;
    for (int i = tid; i < HID; i += OO) sh_h[i] = hLast[b * HID + i];
    __syncthreads();

    float acc = 0.0f;
    const float* w = w_out + (size_t)tid * HID;
#pragma unroll 4
    for (int k = 0; k < HID; k++) acc += w[k] * sh_h[k];
    float logit = acc + b_out[tid];

    red[tid] = logit; __syncthreads();
    for (int s = 128; s > 0; s >>= 1) { if (tid < s) red[tid] = fmaxf(red[tid], red[tid + s]); __syncthreads(); }
    float mx = red[0]; __syncthreads();
    float e = expf(logit - mx);
    red[tid] = e; __syncthreads();
    for (int s = 128; s > 0; s >>= 1) { if (tid < s) red[tid] += red[tid + s]; __syncthreads(); }
    float sum = red[0];
    pred[b * OO + tid] = e / sum;
}

// ---------------- launch ----------------
extern "C" void kernel_launch(void* const* d_in, const int* in_sizes, int n_in,
                              void* d_out, int out_size) {
    const float* x     = (const float*)d_in[0];
    const float* w_ih0 = (const float*)d_in[1];
    const float* w_hh0 = (const float*)d_in[2];
    const float* bias0 = (const float*)d_in[3];
    const float* thr0  = (const float*)d_in[4];
    const float* w_ih1 = (const float*)d_in[6];
    const float* w_hh1 = (const float*)d_in[7];
    const float* bias1 = (const float*)d_in[8];
    const float* thr1  = (const float*)d_in[9];
    const float* w_out = (const float*)d_in[11];
    const float* b_out = (const float*)d_in[12];

    float* out  = (float*)d_out;
    float* pred = out;
    float* hs   = out + B * OO;
    float* cs   = hs + (size_t)T * B * HID;
    float* os   = cs + (size_t)T * B * HID;
    float* is_  = os + (size_t)T * B * HID;

    const int SMEM0 = (HID + D) * 24 * 4 + 16 * 32 * 17 * 4;    // 157,696 B
    const int SMEM1 = (2 * HID) * 24 * 4 + 16 * 32 * 17 * 4;    // 231,424 B
    cudaFuncSetAttribute(scan_kernel<0>, cudaFuncAttributeMaxDynamicSharedMemorySize, SMEM0);
    cudaFuncSetAttribute(scan_kernel<1>, cudaFuncAttributeMaxDynamicSharedMemorySize, SMEM1);

    dim3 tpt(32, 8);
    // ALL prologue work hoisted before scan0 (no bubble between the scans)
    pack_kernel<<<dim3(HID / 32, G3 / 32), tpt>>>(w_hh0, 0, HID, 0);
    pack_kernel<<<dim3(D / 32, G3 / 32), tpt>>>(w_ih0, 0, D, HID);
    pack_kernel<<<dim3(HID / 32, G3 / 32), tpt>>>(w_hh1, 1, HID, 0);
    pack_kernel<<<dim3(HID / 32, G3 / 32), tpt>>>(w_ih1, 1, HID, HID);
    xpose_kernel<<<T * D / 32, tpt>>>(x);          // zeroes both states + barriers

    scan_kernel<0><<<NBLK, THR, SMEM0>>>(bias0, thr0, nullptr, nullptr, nullptr, nullptr);
    scan_kernel<1><<<NBLK, THR, SMEM1>>>(bias1, thr1, hs, cs, os, is_);

    head_kernel<<<B, OO>>>(hs + (size_t)(T - 1) * B * HID, w_out, b_out, pred);
}

// round 16
// speedup vs baseline: 1.2440x; 1.0005x over previous
#include <cuda_runtime.h>
#include <math.h>

// Problem constants
#define B    32
#define T    256
#define D    256
#define HID  1024
#define G3   3072
#define OO   256
#define ALPHA 0.001f
#define ONEMA 0.999f

#define NBLK 128          // one block per 8 output columns (128*8 = 1024)
#define THR  512          // 16 warps = 16 k-chunks

typedef unsigned long long u64;

// ---------------- static device scratch (allocation-free) ----------------
__device__ float g_WT0[(HID + D) * G3];        // 1280 x 3072 k-major
__device__ float g_WT1[(2 * HID) * G3];        // 2048 x 3072 k-major
__device__ float g_xT[(size_t)T * D * 32];     // transposed input [t*D+d][b]
__device__ float g_o0[(size_t)T * HID * 32];   // layer0 events [t][j][b]
__device__ float g_sh0[2][HID * 32];           // L0 h = o*c, double-buffered
__device__ float g_sh1[2][HID * 32];           // L1 h = o*c, double-buffered
__device__ unsigned g_bar_cnt0, g_bar_cnt1;
__device__ volatile unsigned g_bar_gen0;
__device__ volatile unsigned g_bar_gen1;

__device__ __forceinline__ float sigmoidf_(float v) { return 1.0f / (1.0f + expf(-v)); }

__device__ __forceinline__ void ffma2(u64& d, u64 a, u64 b) {
    asm("fma.rn.f32x2 %0, %1, %2, %0;" : "+l"(d) : "l"(a), "l"(b));
}
__device__ __forceinline__ u64 packdup(float a) {
    u64 r; unsigned ua = __float_as_uint(a);
    asm("mov.b64 %0, {%1, %1};" : "=l"(r) : "r"(ua));
    return r;
}
__device__ __forceinline__ void unpack2(u64 v, float& lo, float& hi) {
    unsigned l, h;
    asm("mov.b64 {%0, %1}, %2;" : "=r"(l), "=r"(h) : "l"(v));
    lo = __uint_as_float(l); hi = __uint_as_float(h);
}

// ---------------- grid-wide barrier (round-10 version, per-layer vars) --------
template <int LAYER>
__device__ __forceinline__ void gbar(unsigned target) {
    unsigned* cnt = (LAYER == 0) ? &g_bar_cnt0 : &g_bar_cnt1;
    volatile unsigned* gen = (LAYER == 0) ? &g_bar_gen0 : &g_bar_gen1;
    __syncthreads();
    if (threadIdx.x == 0) {
        __threadfence();
        unsigned old = atomicAdd(cnt, 1u);
        if (old == NBLK - 1u) {
            *cnt = 0u;
            __threadfence();
            *gen = target;
        } else {
            while (*gen != target) { }
        }
        __threadfence();
    }
    __syncthreads();
}

// ---------------- fused prologue: all packs + xpose + init in ONE kernel ------
// Segments (flattened 1D grid, 256 threads each):
//   [0,3072)      pack w_hh0 -> WT0 rows [0,1024)
//   [3072,3840)   pack w_ih0 -> WT0 rows [1024,1280)
//   [3840,6912)   pack w_hh1 -> WT1 rows [0,1024)
//   [6912,9984)   pack w_ih1 -> WT1 rows [1024,2048)
//   [9984,12032)  x transpose + state/barrier init
__global__ void prologue_kernel(const float* __restrict__ x,
                                const float* __restrict__ w_hh0,
                                const float* __restrict__ w_ih0,
                                const float* __restrict__ w_hh1,
                                const float* __restrict__ w_ih1) {
    __shared__ float tile[32][33];
    const int tid = threadIdx.x;
    const int tx = tid & 31;
    const int ty = tid >> 5;                  // 0..7
    int bid = blockIdx.x;

    if (bid < 9984) {
        // ---- weight pack segment ----
        const float* src;
        float* dst;
        int K, rowOff, tilei;
        if (bid < 3072)      { src = w_hh0; dst = g_WT0; K = HID; rowOff = 0;    tilei = bid; }
        else if (bid < 3840) { src = w_ih0; dst = g_WT0; K = D;   rowOff = HID;  tilei = bid - 3072; }
        else if (bid < 6912) { src = w_hh1; dst = g_WT1; K = HID; rowOff = 0;    tilei = bid - 3840; }
        else                 { src = w_ih1; dst = g_WT1; K = HID; rowOff = HID;  tilei = bid - 6912; }
        const int nk = K >> 5;
        const int kBase = (tilei % nk) * 32;
        const int colBase = (tilei / nk) * 32;
#pragma unroll
        for (int i = 0; i < 32; i += 8) {
            int col = colBase + ty + i;
            tile[ty + i][tx] = src[(size_t)col * K + kBase + tx];
        }
        __syncthreads();
#pragma unroll
        for (int i = 0; i < 32; i += 8) {
            int k = kBase + ty + i;
            dst[(size_t)(k + rowOff) * G3 + colBase + tx] = tile[tx][ty + i];
        }
    } else {
        // ---- x transpose + state/barrier init ----
        const int xt = bid - 9984;            // 0..2047
        const int col0 = xt * 32;             // td tile
        int gidx = xt * 256 + tid;
        if (gidx < HID * 32) {
            g_sh0[0][gidx] = 0.0f; g_sh0[1][gidx] = 0.0f;
            g_sh1[0][gidx] = 0.0f; g_sh1[1][gidx] = 0.0f;
        }
        if (gidx == 0) {
            g_bar_cnt0 = 0u; g_bar_gen0 = 0u;
            g_bar_cnt1 = 0u; g_bar_gen1 = 0u;
        }
#pragma unroll
        for (int i = 0; i < 32; i += 8) {
            int b = ty + i;
            tile[b][tx] = x[(size_t)b * (T * D) + col0 + tx];
        }
        __syncthreads();
#pragma unroll
        for (int i = 0; i < 32; i += 8) {
            int td = col0 + ty + i;
            g_xT[(size_t)td * 32 + tx] = tile[tx][ty + i];
        }
    }
}

// store 2 gates (8 floats each) into exchange buffer row, pitch 17
__device__ __forceinline__ void store16(float* p, const u64* a, const u64* b) {
    float lo, hi;
    unpack2(a[0], lo, hi); p[0] = lo; p[1] = hi;
    unpack2(a[1], lo, hi); p[2] = lo; p[3] = hi;
    unpack2(a[2], lo, hi); p[4] = lo; p[5] = hi;
    unpack2(a[3], lo, hi); p[6] = lo; p[7] = hi;
    unpack2(b[0], lo, hi); p[8]  = lo; p[9]  = hi;
    unpack2(b[1], lo, hi); p[10] = lo; p[11] = hi;
    unpack2(b[2], lo, hi); p[12] = lo; p[13] = hi;
    unpack2(b[3], lo, hi); p[14] = lo; p[15] = hi;
}

// One k-segment of GEMM with 8-deep activation prefetch (round-10 form).
// cnt is a multiple of 8. Accumulation order = serial k-ascending (bitwise).
#define GEMM_SEG(cnt, aptr, AC)                                              \
    for (int kt = 0; kt < (cnt); kt += 8) {                                  \
        float a8[8];                                                         \
        _Pragma("unroll")                                                    \
        for (int i = 0; i < 8; i++) a8[i] = (aptr)[(size_t)(kt + i) * 32];   \
        _Pragma("unroll")                                                    \
        for (int i = 0; i < 8; i++) {                                        \
            u64 aa = packdup(a8[i]);                                         \
            longlong2 p0 = wr[0], p1 = wr[1], p2 = wr[2];                    \
            longlong2 p3 = wr[3], p4 = wr[4], p5 = wr[5];                    \
            ffma2(aU[0], (u64)p0.x, aa); ffma2(aU[1], (u64)p0.y, aa);        \
            ffma2(aU[2], (u64)p1.x, aa); ffma2(aU[3], (u64)p1.y, aa);        \
            ffma2(aR[0], (u64)p2.x, aa); ffma2(aR[1], (u64)p2.y, aa);        \
            ffma2(aR[2], (u64)p3.x, aa); ffma2(aR[3], (u64)p3.y, aa);        \
            ffma2(AC[0], (u64)p4.x, aa); ffma2(AC[1], (u64)p4.y, aa);        \
            ffma2(AC[2], (u64)p5.x, aa); ffma2(AC[3], (u64)p5.y, aa);        \
            wr += 6;                                                         \
        }                                                                    \
    }

// ---------------- persistent scan kernel (round-10 structure) ----------------
// grid = 128 blocks, each owns 8 j-columns; warp w = contiguous k-chunk w.
// All 16 warps GEMM concurrently; per-gate chunk sums in serial s=0..15 order.
// Register-resident c/o/i state. Final-step grid barrier skipped.
template <int LAYER>
__global__ __launch_bounds__(THR, 1) void scan_kernel(
    const float* __restrict__ bias,
    const float* __restrict__ thr_raw,
    float* __restrict__ hs, float* __restrict__ cs,
    float* __restrict__ os, float* __restrict__ is_)
{
    constexpr int KX    = (LAYER == 0) ? D : HID;    // x-part K
    constexpr int KT    = HID + KX;                  // total K
    constexpr int CK    = KT / 16;                   // 80 / 128 per warp-chunk
    constexpr int CH_HI = (LAYER == 0) ? 13 : 8;     // chunks with hidden rows
    constexpr int CX_LO = (LAYER == 0) ? 12 : 8;     // chunks with x rows
    const float* __restrict__ WT = (LAYER == 0) ? g_WT0 : g_WT1;

    extern __shared__ float smem[];
    float* s_w = smem;                               // [KT][24]
    float* s_p = smem + KT * 24;                     // [16][32] pitch 17 exchange

    const int tid  = threadIdx.x;
    const int lane = tid & 31;                       // = batch in GEMM
    const int wrp  = tid >> 5;                       // = k-chunk index
    const int jb   = blockIdx.x * 8;                 // block's 8 j-columns

    // ---- stage weights into smem once ----
    for (int i = tid; i < KT * 6; i += THR) {
        int k = i / 6, c = i - k * 6;
        int g = c >> 1, half = c & 1;
        float4 v = *(const float4*)(WT + (size_t)k * G3 + g * HID + jb + half * 4);
        ((float4*)(s_w + k * 24))[c] = v;
    }

    // update-phase constants + register state (tid<256: fj=tid&7, fb=tid>>3)
    const int fj = tid & 7;
    const int fb = tid >> 3;
    const int jg = jb + fj;
    float thv = 0.f, bU = 0.f, bR = 0.f, bC = 0.f;
    float rc = 0.f, ro = 0.f, riu = 0.f, rir = 0.f, ric = 0.f;   // c,o,i state
    if (tid < 256) {
        thv = sigmoidf_(thr_raw[jg]);
        bU = bias[jg]; bR = bias[HID + jg]; bC = bias[2 * HID + jg];
    }
    __syncthreads();

    const int k0 = wrp * CK;
    int hEnd = HID - k0;                             // hidden rows in this chunk
    if (hEnd < 0) hEnd = 0;
    if (hEnd > CK) hEnd = CK;
    const int xCnt = CK - hEnd;
    const int kx0 = k0 + hEnd - HID;                 // x-row start (valid iff xCnt>0)
    float* myrow = s_p + (wrp * 32 + lane) * 17;

    unsigned gen = 0;

    for (int t = 0; t < T; t++) {
        const float* __restrict__ shR = (LAYER == 0) ? g_sh0[t & 1] : g_sh1[t & 1];
        float* __restrict__ shW = (LAYER == 0) ? g_sh0[(t & 1) ^ 1] : g_sh1[(t & 1) ^ 1];

        // ---- GEMM: serial over this warp's contiguous chunk, 8-deep prefetch ----
        u64 aU[4], aR[4], aCH[4], aCX[4];
#pragma unroll
        for (int i = 0; i < 4; i++) { aU[i] = 0; aR[i] = 0; aCH[i] = 0; aCX[i] = 0; }

        const longlong2* wr = (const longlong2*)(s_w + (size_t)k0 * 24);
        if (hEnd > 0) {                              // hidden rows -> aCH
            const float* ah = shR + (size_t)k0 * 32 + lane;
            GEMM_SEG(hEnd, ah, aCH)
        }
        if (xCnt > 0) {                              // x rows -> aCX
            const float* ax = (LAYER == 0)
                ? g_xT + ((size_t)t * D + kx0) * 32 + lane
                : g_o0 + ((size_t)t * HID + kx0) * 32 + lane;
            GEMM_SEG(xCnt, ax, aCX)
        }

        // ---- exchange round 1: U, R ----
        store16(myrow, aU, aR);
        __syncthreads();
        float su = 0.f, sr = 0.f;
        if (tid < 256) {
#pragma unroll
            for (int s = 0; s < 16; s++) {
                const float* q = s_p + (s * 32 + fb) * 17;
                su += q[fj];
                sr += q[8 + fj];
            }
        }
        __syncthreads();

        // ---- exchange round 2: CH, CX ----
        store16(myrow, aCH, aCX);
        __syncthreads();
        float sch = 0.f, scx = 0.f;
        if (tid < 256) {
#pragma unroll
            for (int s = 0; s < 16; s++) {
                const float* q = s_p + (s * 32 + fb) * 17;
                if (s < CH_HI) sch += q[fj];
                if (s >= CX_LO) scx += q[8 + fj];
            }
        }

        // ---- EGRU update: one (b, j) per thread, register state ----
        if (tid < 256) {
            float niu = ALPHA * riu + ONEMA * (su + bU);
            float u = sigmoidf_(niu);
            float nir = ALPHA * rir + ONEMA * (sr + bR);
            float r = sigmoidf_(nir);
            float nic = ALPHA * ric + ONEMA * (scx + r * sch + bC);
            float z = tanhf(nic);

            float creset = rc - ro * thv;
            float nc = (1.0f - u) * creset + u * z;
            float no = (nc - thv > 0.0f) ? 1.0f : 0.0f;

            rc = nc; ro = no; riu = niu; rir = nir; ric = nic;

            shW[jg * 32 + fb] = no * nc;

            if (LAYER == 0) {
                g_o0[((size_t)t * HID + jg) * 32 + fb] = no;
            } else {
                size_t ho = (size_t)t * (B * HID) + fb * HID + jg;
                hs[ho] = no * nc;
                cs[ho] = nc;
                os[ho] = no;
                size_t io = (size_t)t * (B * G3) + (size_t)fb * G3 + jg;
                is_[io] = niu;
                is_[io + HID] = nir;
                is_[io + 2 * HID] = nic;
            }
        }
        if (t + 1 < T) gbar<LAYER>(++gen);           // final-step barrier skipped
    }
}

// ---------------- softmax head ----------------
__global__ void head_kernel(const float* __restrict__ hLast,
                            const float* __restrict__ w_out,
                            const float* __restrict__ b_out,
                            float* __restrict__ pred)
{
    __shared__ float sh_h[HID];
    __shared__ float red[OO];
    int b = blockIdx.x, tid = threadIdx.x;
    for (int i = tid; i < HID; i += OO) sh_h[i] = hLast[b * HID + i];
    __syncthreads();

    float acc = 0.0f;
    const float* w = w_out + (size_t)tid * HID;
#pragma unroll 4
    for (int k = 0; k < HID; k++) acc += w[k] * sh_h[k];
    float logit = acc + b_out[tid];

    red[tid] = logit; __syncthreads();
    for (int s = 128; s > 0; s >>= 1) { if (tid < s) red[tid] = fmaxf(red[tid], red[tid + s]); __syncthreads(); }
    float mx = red[0]; __syncthreads();
    float e = expf(logit - mx);
    red[tid] = e; __syncthreads();
    for (int s = 128; s > 0; s >>= 1) { if (tid < s) red[tid] += red[tid + s]; __syncthreads(); }
    float sum = red[0];
    pred[b * OO + tid] = e / sum;
}

// ---------------- launch ----------------
extern "C" void kernel_launch(void* const* d_in, const int* in_sizes, int n_in,
                              void* d_out, int out_size) {
    const float* x     = (const float*)d_in[0];
    const float* w_ih0 = (const float*)d_in[1];
    const float* w_hh0 = (const float*)d_in[2];
    const float* bias0 = (const float*)d_in[3];
    const float* thr0  = (const float*)d_in[4];
    const float* w_ih1 = (const float*)d_in[6];
    const float* w_hh1 = (const float*)d_in[7];
    const float* bias1 = (const float*)d_in[8];
    const float* thr1  = (const float*)d_in[9];
    const float* w_out = (const float*)d_in[11];
    const float* b_out = (const float*)d_in[12];

    float* out  = (float*)d_out;
    float* pred = out;
    float* hs   = out + B * OO;
    float* cs   = hs + (size_t)T * B * HID;
    float* os   = cs + (size_t)T * B * HID;
    float* is_  = os + (size_t)T * B * HID;

    const int SMEM0 = (HID + D) * 24 * 4 + 16 * 32 * 17 * 4;    // 157,696 B
    const int SMEM1 = (2 * HID) * 24 * 4 + 16 * 32 * 17 * 4;    // 231,424 B
    cudaFuncSetAttribute(scan_kernel<0>, cudaFuncAttributeMaxDynamicSharedMemorySize, SMEM0);
    cudaFuncSetAttribute(scan_kernel<1>, cudaFuncAttributeMaxDynamicSharedMemorySize, SMEM1);

    // ONE fused prologue launch: all weight packs + x transpose + state init
    prologue_kernel<<<12032, 256>>>(x, w_hh0, w_ih0, w_hh1, w_ih1);

    scan_kernel<0><<<NBLK, THR, SMEM0>>>(bias0, thr0, nullptr, nullptr, nullptr, nullptr);
    scan_kernel<1><<<NBLK, THR, SMEM1>>>(bias1, thr1, hs, cs, os, is_);

    head_kernel<<<B, OO>>>(hs + (size_t)(T - 1) * B * HID, w_out, b_out, pred);
}